// round 6
// baseline (speedup 1.0000x reference)
#include <cuda_runtime.h>
#include <cuda_fp16.h>
#include <cstdint>

// ---------------------------------------------------------------------------
// PHMLinear via Kronecker factorization, warp-level HMMA (baseline PTX).
//   Per token (X = x row viewed 64x64):  Y = sum_b A_b @ X @ B_b^T + bias
//   U_b = A_b @ X (f32 accum + cvt),  Y += U_b @ B_b^T (f32 accum).
//
// Warp-autonomous version: NO X staging, NO per-tile barriers.
//   - X fragments for GEMM1 (mma B-operand) gathered directly from global
//     fp32 with LDG + cvt, using the m16n8k16 B-fragment lane layout.
//   - smem holds only fp16 A and B weights (128 KB), loaded once.
//   - 384 threads = 12 warps = 6 tokens in flight, 2 warps per token
//     (ihalf split: 32 i-rows per warp so B fragments are shared across rt).
// ---------------------------------------------------------------------------

#define NTOK 16384

#define OFF_A    0        // 512 rows x 128B, fp16 A[(b,i), j], swizzled
#define OFF_B    65536    // 512 rows x 128B, fp16 B[(b,k), m], swizzled
#define SMEM_BYTES 131072

__device__ __forceinline__ uint32_t swz(uint32_t o) { return o ^ ((o >> 3) & 0x70); }

__device__ __forceinline__ uint32_t s2u(const void* p) {
    uint32_t a;
    asm("{ .reg .u64 t; cvta.to.shared.u64 t, %1; cvt.u32.u64 %0, t; }" : "=r"(a) : "l"(p));
    return a;
}
__device__ __forceinline__ uint32_t h2u(__half2 h) { return *reinterpret_cast<uint32_t*>(&h); }

__device__ __forceinline__ void ldsm4(uint32_t a, uint32_t* r) {
    asm volatile("ldmatrix.sync.aligned.m8n8.x4.shared.b16 {%0,%1,%2,%3}, [%4];"
                 : "=r"(r[0]), "=r"(r[1]), "=r"(r[2]), "=r"(r[3]) : "r"(a));
}
__device__ __forceinline__ void mma_f32(float* d, const uint32_t* a, const uint32_t* b) {
    asm volatile(
        "mma.sync.aligned.m16n8k16.row.col.f32.f16.f16.f32 "
        "{%0,%1,%2,%3}, {%4,%5,%6,%7}, {%8,%9}, {%0,%1,%2,%3};"
        : "+f"(d[0]), "+f"(d[1]), "+f"(d[2]), "+f"(d[3])
        : "r"(a[0]), "r"(a[1]), "r"(a[2]), "r"(a[3]), "r"(b[0]), "r"(b[1]));
}

extern __shared__ char smem[];

__global__ void __launch_bounds__(384, 1)
phm_kernel(const float* __restrict__ x, const float* __restrict__ A,
           const float* __restrict__ B, const float* __restrict__ bias,
           float* __restrict__ out)
{
    const int tid  = threadIdx.x;
    const int wid  = tid >> 5;
    const int lane = tid & 31;
    const uint32_t sbase = s2u(smem);

    // ---- one-time: weights fp32 -> fp16 swizzled smem ----
    {
        const float4* Ag = (const float4*)A;   // 8192 float4
        const float4* Bg = (const float4*)B;
        for (int v = tid; v < 8192; v += 384) {
            int row = v >> 4, m4 = v & 15;
            uint32_t off = swz((uint32_t)(row * 128 + m4 * 8));
            float4 f = Ag[v];
            *(uint2*)(smem + OFF_A + off) =
                make_uint2(h2u(__floats2half2_rn(f.x, f.y)), h2u(__floats2half2_rn(f.z, f.w)));
            f = Bg[v];
            *(uint2*)(smem + OFF_B + off) =
                make_uint2(h2u(__floats2half2_rn(f.x, f.y)), h2u(__floats2half2_rn(f.z, f.w)));
        }
    }
    __syncthreads();

    const int tp    = wid >> 1;        // token slot 0..5
    const int ihalf = wid & 1;         // which 32 rows of i
    const int ibase = ihalf << 5;
    const int l16   = lane & 15;       // ldmatrix row component (A pattern)
    const int lhi   = lane >> 4;       // ldmatrix col-half component
    const int b2row = ((lane >> 4) << 3) + (lane & 7);   // B2 pattern row part
    const int b2c   = (lane >> 3) & 1;                   // B2 pattern col part
    const int gi    = lane >> 2;       // mma group row
    const int gk    = (lane & 3) << 1; // mma group col pair

    // X-gather per-lane constants (m16n8k16 B-fragment layout):
    //  reg r of frag (jt,nt): j0 = jt*16 + (lane&3)*2 + 8r ; m = mc*32+nt*8+(lane>>2)
    const int jrow = (lane & 3) << 1;
    const int mcol = lane >> 2;

    const float2* bg = (const float2*)bias;
    const int stride = (int)gridDim.x * 6;

    for (int token = (int)blockIdx.x * 6 + tp; token < NTOK; token += stride) {
        const float* xt = x + (size_t)token * 4096;

        // ---- init Y with bias (L1-resident) ----
        float Y[2][8][4];
        #pragma unroll
        for (int rt = 0; rt < 2; rt++) {
            int i0 = ibase + rt * 16 + gi;
            #pragma unroll
            for (int nt = 0; nt < 8; nt++) {
                int k0 = nt * 8 + gk;
                float2 b01 = __ldg(bg + ((i0 * 64 + k0) >> 1));
                float2 b23 = __ldg(bg + (((i0 + 8) * 64 + k0) >> 1));
                Y[rt][nt][0] = b01.x; Y[rt][nt][1] = b01.y;
                Y[rt][nt][2] = b23.x; Y[rt][nt][3] = b23.y;
            }
        }

        #pragma unroll
        for (int mc = 0; mc < 2; mc++) {
            // ---- gather X B-fragments for this m-chunk directly from gmem ----
            uint32_t XB[4][2][4];
            #pragma unroll
            for (int jt = 0; jt < 4; jt++) {
                #pragma unroll
                for (int nt = 0; nt < 4; nt++) {
                    int m = mc * 32 + nt * 8 + mcol;
                    #pragma unroll
                    for (int r = 0; r < 2; r++) {
                        int j0 = jt * 16 + jrow + r * 8;
                        float f0 = __ldg(xt + j0 * 64 + m);
                        float f1 = __ldg(xt + j0 * 64 + 64 + m);
                        XB[jt][nt >> 1][(nt & 1) * 2 + r] = h2u(__floats2half2_rn(f0, f1));
                    }
                }
            }
            #pragma unroll
            for (int b = 0; b < 8; b++) {
                // ---- GEMM1 (f32 accum): U = A_b[ibase:+32,:] @ X[:, mc*32:+32]
                float U[2][4][4];
                #pragma unroll
                for (int rt = 0; rt < 2; rt++)
                    #pragma unroll
                    for (int nt = 0; nt < 4; nt++)
                        #pragma unroll
                        for (int e = 0; e < 4; e++) U[rt][nt][e] = 0.f;

                #pragma unroll
                for (int jt = 0; jt < 4; jt++) {
                    uint32_t AF[2][4];
                    #pragma unroll
                    for (int rt = 0; rt < 2; rt++) {
                        int row = b * 64 + ibase + rt * 16 + l16;
                        uint32_t c = (uint32_t)(jt * 2 + lhi) ^ (uint32_t)(row & 7);
                        ldsm4(sbase + OFF_A + (uint32_t)(row * 128) + (c << 4), AF[rt]);
                    }
                    #pragma unroll
                    for (int rt = 0; rt < 2; rt++)
                        #pragma unroll
                        for (int nt = 0; nt < 4; nt++)
                            mma_f32(U[rt][nt], AF[rt], XB[jt][nt >> 1] + (nt & 1) * 2);
                }
                // ---- cvt U (f32) -> GEMM2 A-fragments (f16x2) ----
                uint32_t UA[2][2][4];
                #pragma unroll
                for (int rt = 0; rt < 2; rt++)
                    #pragma unroll
                    for (int mt = 0; mt < 2; mt++) {
                        UA[rt][mt][0] = h2u(__floats2half2_rn(U[rt][2*mt][0],   U[rt][2*mt][1]));
                        UA[rt][mt][1] = h2u(__floats2half2_rn(U[rt][2*mt][2],   U[rt][2*mt][3]));
                        UA[rt][mt][2] = h2u(__floats2half2_rn(U[rt][2*mt+1][0], U[rt][2*mt+1][1]));
                        UA[rt][mt][3] = h2u(__floats2half2_rn(U[rt][2*mt+1][2], U[rt][2*mt+1][3]));
                    }
                // ---- GEMM2 (f32 accum): Y += U @ B_b[:, mc*32:+32]^T ----
                #pragma unroll
                for (int kop = 0; kop < 4; kop++) {
                    uint32_t BF[2][4];
                    #pragma unroll
                    for (int mt = 0; mt < 2; mt++) {
                        int row = b * 64 + kop * 16 + b2row;
                        uint32_t c = (uint32_t)(mc * 4 + mt * 2 + b2c) ^ (uint32_t)(lane & 7);
                        ldsm4(sbase + OFF_B + (uint32_t)(row * 128) + (c << 4), BF[mt]);
                    }
                    #pragma unroll
                    for (int mt = 0; mt < 2; mt++)
                        #pragma unroll
                        for (int rt = 0; rt < 2; rt++)
                            #pragma unroll
                            for (int h = 0; h < 2; h++)
                                mma_f32(Y[rt][kop * 2 + h], UA[rt][mt], BF[mt] + h * 2);
                }
            }
        }

        // ---- store Y (bias already included) ----
        float* orow = out + (size_t)token * 4096;
        #pragma unroll
        for (int rt = 0; rt < 2; rt++) {
            int i0 = ibase + rt * 16 + gi;
            #pragma unroll
            for (int nt = 0; nt < 8; nt++) {
                int k0 = nt * 8 + gk;
                *(float2*)(orow + (size_t)i0 * 64 + k0)       = make_float2(Y[rt][nt][0], Y[rt][nt][1]);
                *(float2*)(orow + (size_t)(i0 + 8) * 64 + k0) = make_float2(Y[rt][nt][2], Y[rt][nt][3]);
            }
        }
    }
}

extern "C" void kernel_launch(void* const* d_in, const int* in_sizes, int n_in,
                              void* d_out, int out_size) {
    const float* x    = (const float*)d_in[0];
    const float* A    = (const float*)d_in[1];
    const float* B    = (const float*)d_in[2];
    const float* bias = (const float*)d_in[3];
    float* out        = (float*)d_out;

    cudaFuncSetAttribute(phm_kernel, cudaFuncAttributeMaxDynamicSharedMemorySize, SMEM_BYTES);
    int nsm = 148;
    cudaDeviceGetAttribute(&nsm, cudaDevAttrMultiProcessorCount, 0);
    if (nsm <= 0 || nsm > 1024) nsm = 148;

    phm_kernel<<<nsm, 384, SMEM_BYTES>>>(x, A, B, bias, out);
}

// round 7
// speedup vs baseline: 2.2357x; 2.2357x over previous
#include <cuda_runtime.h>
#include <cuda_fp16.h>
#include <cstdint>

// ---------------------------------------------------------------------------
// PHMLinear via Kronecker factorization, warp-level HMMA (baseline PTX).
//   Per token (X = x row viewed 64x64):  Y = sum_b A_b @ X @ B_b^T + bias
//   U_b = A_b @ X (f32 accum + cvt),  Y += U_b @ B_b^T (f32 accum).
// Persistent, 1 CTA/SM, 256 threads, 4 tokens/iter, 2 warps/token
// (minimal-ldsm mapping, proven in R3), cp.async X double-buffer (R4/R5).
// ---------------------------------------------------------------------------

#define TILES 4096        // 4 tokens per tile, 16384 tokens total

#define OFF_A    0        // 512 rows x 128B, fp16 A[(b,i), j], swizzled
#define OFF_B    65536    // 512 rows x 128B, fp16 B[(b,k), m], swizzled
#define OFF_X    131072   // 4 tokens x 64 rows x 128B, fp16 (converted)
#define OFF_RAW  163840   // 64 KB raw fp32 x tile (cp.async staging)
#define SMEM_BYTES 229376

__device__ __forceinline__ uint32_t swz(uint32_t o) { return o ^ ((o >> 3) & 0x70); }

__device__ __forceinline__ uint32_t s2u(const void* p) {
    uint32_t a;
    asm("{ .reg .u64 t; cvta.to.shared.u64 t, %1; cvt.u32.u64 %0, t; }" : "=r"(a) : "l"(p));
    return a;
}
__device__ __forceinline__ uint32_t h2u(__half2 h) { return *reinterpret_cast<uint32_t*>(&h); }

__device__ __forceinline__ void ldsm4(uint32_t a, uint32_t* r) {
    asm volatile("ldmatrix.sync.aligned.m8n8.x4.shared.b16 {%0,%1,%2,%3}, [%4];"
                 : "=r"(r[0]), "=r"(r[1]), "=r"(r[2]), "=r"(r[3]) : "r"(a));
}
__device__ __forceinline__ void ldsm4t(uint32_t a, uint32_t* r) {
    asm volatile("ldmatrix.sync.aligned.m8n8.x4.trans.shared.b16 {%0,%1,%2,%3}, [%4];"
                 : "=r"(r[0]), "=r"(r[1]), "=r"(r[2]), "=r"(r[3]) : "r"(a));
}
__device__ __forceinline__ void mma_f32(float* d, const uint32_t* a, const uint32_t* b) {
    asm volatile(
        "mma.sync.aligned.m16n8k16.row.col.f32.f16.f16.f32 "
        "{%0,%1,%2,%3}, {%4,%5,%6,%7}, {%8,%9}, {%0,%1,%2,%3};"
        : "+f"(d[0]), "+f"(d[1]), "+f"(d[2]), "+f"(d[3])
        : "r"(a[0]), "r"(a[1]), "r"(a[2]), "r"(a[3]), "r"(b[0]), "r"(b[1]));
}

#define CP_ASYNC16(s, g) \
    asm volatile("cp.async.cg.shared.global [%0], [%1], 16;" :: "r"(s), "l"(g) : "memory")
#define CP_COMMIT()  asm volatile("cp.async.commit_group;" ::: "memory")
#define CP_WAIT0()   asm volatile("cp.async.wait_group 0;" ::: "memory")

extern __shared__ char smem[];

__global__ void __launch_bounds__(256, 1)
phm_kernel(const float* __restrict__ x, const float* __restrict__ A,
           const float* __restrict__ B, const float* __restrict__ bias,
           float* __restrict__ out)
{
    const int tid  = threadIdx.x;
    const int wid  = tid >> 5;
    const int lane = tid & 31;
    const uint32_t sbase = s2u(smem);
    const uint32_t sraw  = sbase + OFF_RAW;

    // ---- prefetch first x tile via cp.async (overlaps weight staging) ----
    int tile0 = blockIdx.x;
    if (tile0 < TILES) {
        const char* gx = (const char*)x + (size_t)tile0 * 65536;
        #pragma unroll
        for (int p = 0; p < 16; p++) {
            int v = tid + (p << 8);
            CP_ASYNC16(sraw + v * 16, gx + (size_t)v * 16);
        }
    }
    CP_COMMIT();

    // ---- one-time: weights fp32 -> fp16 swizzled smem ----
    {
        const float4* Ag = (const float4*)A;   // 8192 float4
        const float4* Bg = (const float4*)B;
        #pragma unroll
        for (int p = 0; p < 32; p++) {
            int v = tid + (p << 8);
            int row = v >> 4, m4 = v & 15;
            uint32_t off = swz((uint32_t)(row * 128 + m4 * 8));
            float4 f = Ag[v];
            *(uint2*)(smem + OFF_A + off) =
                make_uint2(h2u(__floats2half2_rn(f.x, f.y)), h2u(__floats2half2_rn(f.z, f.w)));
            f = Bg[v];
            *(uint2*)(smem + OFF_B + off) =
                make_uint2(h2u(__floats2half2_rn(f.x, f.y)), h2u(__floats2half2_rn(f.z, f.w)));
        }
    }

    const int tl    = wid >> 1;        // token slot 0..3 within tile
    const int ihalf = wid & 1;         // which 32 rows of i
    const int ibase = ihalf << 5;
    const int l16   = lane & 15;       // ldmatrix row component (A, X patterns)
    const int lhi   = lane >> 4;       // ldmatrix col-half component
    const int b2row = ((lane >> 4) << 3) + (lane & 7);   // B2 pattern row part
    const int b2c   = (lane >> 3) & 1;                   // B2 pattern col part
    const int gi    = lane >> 2;       // mma group row
    const int gk    = (lane & 3) << 1; // mma group col pair

    const uint32_t Xt = sbase + OFF_X + tl * 8192;
    const float2* bg = (const float2*)bias;

    for (int tile = tile0; tile < TILES; tile += (int)gridDim.x) {
        // ---- raw fp32 tile ready -> convert smem->smem to fp16 swizzled ----
        CP_WAIT0();
        __syncthreads();
        #pragma unroll
        for (int p = 0; p < 16; p++) {
            int v = tid + (p << 8);          // 0..4095 float4s
            float4 f = *(const float4*)(smem + OFF_RAW + (size_t)v * 16);
            int w = v & 1023, row = w >> 4, m4 = w & 15;
            uint32_t off = (uint32_t)((v >> 10) * 8192) + swz((uint32_t)(row * 128 + m4 * 8));
            *(uint2*)(smem + OFF_X + off) =
                make_uint2(h2u(__floats2half2_rn(f.x, f.y)), h2u(__floats2half2_rn(f.z, f.w)));
        }
        __syncthreads();

        // ---- kick off next tile's raw load (overlaps compute below) ----
        {
            int nxt = tile + (int)gridDim.x;
            if (nxt < TILES) {
                const char* gx = (const char*)x + (size_t)nxt * 65536;
                #pragma unroll
                for (int p = 0; p < 16; p++) {
                    int v = tid + (p << 8);
                    CP_ASYNC16(sraw + v * 16, gx + (size_t)v * 16);
                }
            }
            CP_COMMIT();
        }

        // ---- init Y with bias (L1-resident after first tile) ----
        float Y[2][8][4];
        #pragma unroll
        for (int rt = 0; rt < 2; rt++) {
            int i0 = ibase + rt * 16 + gi;
            #pragma unroll
            for (int nt = 0; nt < 8; nt++) {
                int k0 = nt * 8 + gk;
                float2 b01 = __ldg(bg + ((i0 * 64 + k0) >> 1));
                float2 b23 = __ldg(bg + (((i0 + 8) * 64 + k0) >> 1));
                Y[rt][nt][0] = b01.x; Y[rt][nt][1] = b01.y;
                Y[rt][nt][2] = b23.x; Y[rt][nt][3] = b23.y;
            }
        }

        #pragma unroll
        for (int mc = 0; mc < 2; mc++) {
            // X B-fragments for this m-chunk (shared across all b)
            uint32_t XB[4][2][4];
            #pragma unroll
            for (int jt = 0; jt < 4; jt++) {
                int row = jt * 16 + l16;
                #pragma unroll
                for (int ntp = 0; ntp < 2; ntp++) {
                    uint32_t c = (uint32_t)(mc * 4 + ntp * 2 + lhi) ^ (uint32_t)(row & 7);
                    ldsm4t(Xt + (uint32_t)(row * 128) + (c << 4), XB[jt][ntp]);
                }
            }
            #pragma unroll
            for (int b = 0; b < 8; b++) {
                // ---- GEMM1 (f32 accum): U = A_b[ibase:+32,:] @ X[:, mc*32:+32]
                float U[2][4][4];
                #pragma unroll
                for (int rt = 0; rt < 2; rt++)
                    #pragma unroll
                    for (int nt = 0; nt < 4; nt++)
                        #pragma unroll
                        for (int e = 0; e < 4; e++) U[rt][nt][e] = 0.f;

                #pragma unroll
                for (int jt = 0; jt < 4; jt++) {
                    uint32_t AF[2][4];
                    #pragma unroll
                    for (int rt = 0; rt < 2; rt++) {
                        int row = b * 64 + ibase + rt * 16 + l16;
                        uint32_t c = (uint32_t)(jt * 2 + lhi) ^ (uint32_t)(row & 7);
                        ldsm4(sbase + OFF_A + (uint32_t)(row * 128) + (c << 4), AF[rt]);
                    }
                    #pragma unroll
                    for (int rt = 0; rt < 2; rt++)
                        #pragma unroll
                        for (int nt = 0; nt < 4; nt++)
                            mma_f32(U[rt][nt], AF[rt], XB[jt][nt >> 1] + (nt & 1) * 2);
                }

                // ---- prefetch all GEMM2 B fragments (independent of cvt) ----
                uint32_t BF[4][2][4];
                #pragma unroll
                for (int kop = 0; kop < 4; kop++)
                    #pragma unroll
                    for (int mt = 0; mt < 2; mt++) {
                        int row = b * 64 + kop * 16 + b2row;
                        uint32_t c = (uint32_t)(mc * 4 + mt * 2 + b2c) ^ (uint32_t)(lane & 7);
                        ldsm4(sbase + OFF_B + (uint32_t)(row * 128) + (c << 4), BF[kop][mt]);
                    }

                // ---- cvt U (f32) -> GEMM2 A-fragments (f16x2), overlaps ldsm ----
                uint32_t UA[2][2][4];
                #pragma unroll
                for (int rt = 0; rt < 2; rt++)
                    #pragma unroll
                    for (int mt = 0; mt < 2; mt++) {
                        UA[rt][mt][0] = h2u(__floats2half2_rn(U[rt][2*mt][0],   U[rt][2*mt][1]));
                        UA[rt][mt][1] = h2u(__floats2half2_rn(U[rt][2*mt][2],   U[rt][2*mt][3]));
                        UA[rt][mt][2] = h2u(__floats2half2_rn(U[rt][2*mt+1][0], U[rt][2*mt+1][1]));
                        UA[rt][mt][3] = h2u(__floats2half2_rn(U[rt][2*mt+1][2], U[rt][2*mt+1][3]));
                    }

                // ---- GEMM2 (f32 accum): Y += U @ B_b[:, mc*32:+32]^T ----
                #pragma unroll
                for (int kop = 0; kop < 4; kop++)
                    #pragma unroll
                    for (int mt = 0; mt < 2; mt++)
                        #pragma unroll
                        for (int rt = 0; rt < 2; rt++)
                            #pragma unroll
                            for (int h = 0; h < 2; h++)
                                mma_f32(Y[rt][kop * 2 + h], UA[rt][mt], BF[kop][mt] + h * 2);
            }
        }

        // ---- store Y (bias already included) ----
        float* orow = out + ((size_t)tile * 4 + tl) * 4096;
        #pragma unroll
        for (int rt = 0; rt < 2; rt++) {
            int i0 = ibase + rt * 16 + gi;
            #pragma unroll
            for (int nt = 0; nt < 8; nt++) {
                int k0 = nt * 8 + gk;
                *(float2*)(orow + (size_t)i0 * 64 + k0)       = make_float2(Y[rt][nt][0], Y[rt][nt][1]);
                *(float2*)(orow + (size_t)(i0 + 8) * 64 + k0) = make_float2(Y[rt][nt][2], Y[rt][nt][3]);
            }
        }
        __syncthreads();   // all warps done with X before next convert
    }
}

extern "C" void kernel_launch(void* const* d_in, const int* in_sizes, int n_in,
                              void* d_out, int out_size) {
    const float* x    = (const float*)d_in[0];
    const float* A    = (const float*)d_in[1];
    const float* B    = (const float*)d_in[2];
    const float* bias = (const float*)d_in[3];
    float* out        = (float*)d_out;

    cudaFuncSetAttribute(phm_kernel, cudaFuncAttributeMaxDynamicSharedMemorySize, SMEM_BYTES);
    int nsm = 148;
    cudaDeviceGetAttribute(&nsm, cudaDevAttrMultiProcessorCount, 0);
    if (nsm <= 0 || nsm > 1024) nsm = 148;
    if (nsm > TILES) nsm = TILES;

    phm_kernel<<<nsm, 256, SMEM_BYTES>>>(x, A, B, bias, out);
}